// round 1
// baseline (speedup 1.0000x reference)
#include <cuda_runtime.h>

// GumbelSoftmaxVectorQuantizer — round 1 baseline
//
// K1: fp32 SGEMM 128x128x16 (double-buffered, 8x8 per thread) computing
//     logits_adj = (x@W + b + gumbel) / TAU  -> 256MB __device__ scratch
// K2: per-(b,t,g) group of V=1024: max/argmax (first-occurrence tie-break),
//     softmax, probs write, codebook gather, ids write. Padding zeroes
//     probs/quantized and sets ids=-1, matching the reference exactly.

static constexpr int Mx = 16384;   // B*T
static constexpr int Kx = 1024;    // Din
static constexpr int Nx = 4096;    // G*V
static constexpr int Gx = 4;
static constexpr int Vx = 1024;
static constexpr int Dx = 128;
static constexpr float INV_TAU = 0.5f;   // TAU = 2.0

// scratch for adjusted logits (allocation-free rule: __device__ global)
__device__ float g_logits[(size_t)Mx * Nx];

__global__ __launch_bounds__(256, 2)
void gemm_epilogue_kernel(const float* __restrict__ A,      // [M,K] inputs
                          const float* __restrict__ W,      // [K,N]
                          const float* __restrict__ bias,   // [N]
                          const float* __restrict__ gum)    // [M,N]
{
    __shared__ float As[2][16][132];   // [buf][k][m], padded rows
    __shared__ float Bs[2][16][128];   // [buf][k][n]

    const int tid  = threadIdx.x;
    const int bm   = blockIdx.y * 128;
    const int bn   = blockIdx.x * 128;

    // global->smem load mapping
    const int arow = tid >> 2;           // 0..63 (and +64)
    const int ak   = (tid & 3) << 2;     // k offset 0,4,8,12
    const int brow = tid >> 5;           // 0..7 (and +8)
    const int bcol = (tid & 31) << 2;    // 0..124

    // compute mapping: 16x16 threads, 8x8 micro-tile each
    const int row0 = (tid >> 4) << 3;
    const int col0 = (tid & 15) << 3;

    const float* Ab = A + (size_t)bm * Kx;

    float acc[8][8];
#pragma unroll
    for (int i = 0; i < 8; i++)
#pragma unroll
        for (int j = 0; j < 8; j++) acc[i][j] = 0.f;

    // prologue: tile 0
    {
        float4 a0 = *(const float4*)&Ab[(size_t)arow        * Kx + ak];
        float4 a1 = *(const float4*)&Ab[(size_t)(arow + 64) * Kx + ak];
        float4 b0 = *(const float4*)&W[(size_t)brow       * Nx + bn + bcol];
        float4 b1 = *(const float4*)&W[(size_t)(brow + 8) * Nx + bn + bcol];
        As[0][ak + 0][arow] = a0.x; As[0][ak + 1][arow] = a0.y;
        As[0][ak + 2][arow] = a0.z; As[0][ak + 3][arow] = a0.w;
        As[0][ak + 0][arow + 64] = a1.x; As[0][ak + 1][arow + 64] = a1.y;
        As[0][ak + 2][arow + 64] = a1.z; As[0][ak + 3][arow + 64] = a1.w;
        *(float4*)&Bs[0][brow][bcol]     = b0;
        *(float4*)&Bs[0][brow + 8][bcol] = b1;
    }
    __syncthreads();

    int buf = 0;
#pragma unroll 1
    for (int kt = 0; kt < Kx; kt += 16) {
        float4 a0n, a1n, b0n, b1n;
        const bool has = (kt + 16) < Kx;
        if (has) {
            const int k2 = kt + 16;
            a0n = *(const float4*)&Ab[(size_t)arow        * Kx + k2 + ak];
            a1n = *(const float4*)&Ab[(size_t)(arow + 64) * Kx + k2 + ak];
            b0n = *(const float4*)&W[(size_t)(k2 + brow)     * Nx + bn + bcol];
            b1n = *(const float4*)&W[(size_t)(k2 + brow + 8) * Nx + bn + bcol];
        }

#pragma unroll
        for (int kk = 0; kk < 16; kk++) {
            float a[8], b[8];
            *(float4*)&a[0] = *(const float4*)&As[buf][kk][row0];
            *(float4*)&a[4] = *(const float4*)&As[buf][kk][row0 + 4];
            *(float4*)&b[0] = *(const float4*)&Bs[buf][kk][col0];
            *(float4*)&b[4] = *(const float4*)&Bs[buf][kk][col0 + 4];
#pragma unroll
            for (int i = 0; i < 8; i++)
#pragma unroll
                for (int j = 0; j < 8; j++)
                    acc[i][j] = fmaf(a[i], b[j], acc[i][j]);
        }

        if (has) {
            buf ^= 1;
            As[buf][ak + 0][arow] = a0n.x; As[buf][ak + 1][arow] = a0n.y;
            As[buf][ak + 2][arow] = a0n.z; As[buf][ak + 3][arow] = a0n.w;
            As[buf][ak + 0][arow + 64] = a1n.x; As[buf][ak + 1][arow + 64] = a1n.y;
            As[buf][ak + 2][arow + 64] = a1n.z; As[buf][ak + 3][arow + 64] = a1n.w;
            *(float4*)&Bs[buf][brow][bcol]     = b0n;
            *(float4*)&Bs[buf][brow + 8][bcol] = b1n;
            __syncthreads();
        }
    }

    // epilogue: + bias + gumbel, * 1/TAU, write scratch
    float bc[8];
    *(float4*)&bc[0] = *(const float4*)&bias[bn + col0];
    *(float4*)&bc[4] = *(const float4*)&bias[bn + col0 + 4];

#pragma unroll
    for (int i = 0; i < 8; i++) {
        const size_t base = (size_t)(bm + row0 + i) * Nx + bn + col0;
        float4 g0 = *(const float4*)&gum[base];
        float4 g1 = *(const float4*)&gum[base + 4];
        float4 o0, o1;
        o0.x = (acc[i][0] + bc[0] + g0.x) * INV_TAU;
        o0.y = (acc[i][1] + bc[1] + g0.y) * INV_TAU;
        o0.z = (acc[i][2] + bc[2] + g0.z) * INV_TAU;
        o0.w = (acc[i][3] + bc[3] + g0.w) * INV_TAU;
        o1.x = (acc[i][4] + bc[4] + g1.x) * INV_TAU;
        o1.y = (acc[i][5] + bc[5] + g1.y) * INV_TAU;
        o1.z = (acc[i][6] + bc[6] + g1.z) * INV_TAU;
        o1.w = (acc[i][7] + bc[7] + g1.w) * INV_TAU;
        *(float4*)&g_logits[base]     = o0;
        *(float4*)&g_logits[base + 4] = o1;
    }
}

__global__ __launch_bounds__(128)
void softmax_kernel(const int*   __restrict__ pads,       // [M] (B*T)
                    const float* __restrict__ codebook,   // [G,V,D]
                    float*       __restrict__ ids_out,    // [M*G]
                    float*       __restrict__ quant_out,  // [M, G*D]
                    float*       __restrict__ probs_out)  // [M*G, V]
{
    const int grp  = blockIdx.x;       // row*G + g
    const int row  = grp >> 2;
    const int g    = grp & 3;
    const int tid  = threadIdx.x;
    const int lane = tid & 31;
    const int warp = tid >> 5;

    const float* base = g_logits + (size_t)grp * Vx;

    float v[8];
    *(float4*)&v[0] = *(const float4*)&base[tid * 8];
    *(float4*)&v[4] = *(const float4*)&base[tid * 8 + 4];

    // local max + first-occurrence argmax
    float m = v[0]; int mi = tid * 8;
#pragma unroll
    for (int j = 1; j < 8; j++)
        if (v[j] > m) { m = v[j]; mi = tid * 8 + j; }

#pragma unroll
    for (int off = 16; off > 0; off >>= 1) {
        float om = __shfl_down_sync(0xffffffffu, m, off);
        int   oi = __shfl_down_sync(0xffffffffu, mi, off);
        if (om > m || (om == m && oi < mi)) { m = om; mi = oi; }
    }

    __shared__ float swarp[4];
    __shared__ int   sidx[4];
    __shared__ float red_m;
    __shared__ int   red_i;
    __shared__ float red_s;

    if (lane == 0) { swarp[warp] = m; sidx[warp] = mi; }
    __syncthreads();
    if (tid == 0) {
        float bmv = swarp[0]; int bi = sidx[0];
        for (int w = 1; w < 4; w++)
            if (swarp[w] > bmv || (swarp[w] == bmv && sidx[w] < bi)) {
                bmv = swarp[w]; bi = sidx[w];
            }
        red_m = bmv; red_i = bi;
    }
    __syncthreads();
    const float mx = red_m;

    float e[8]; float s = 0.f;
#pragma unroll
    for (int j = 0; j < 8; j++) { e[j] = __expf(v[j] - mx); s += e[j]; }
#pragma unroll
    for (int off = 16; off > 0; off >>= 1)
        s += __shfl_down_sync(0xffffffffu, s, off);
    if (lane == 0) swarp[warp] = s;
    __syncthreads();
    if (tid == 0) red_s = swarp[0] + swarp[1] + swarp[2] + swarp[3];
    __syncthreads();

    const int   pad = pads[row];
    const float inv = pad ? 0.f : (1.f / red_s);

    float4 p0, p1;
    p0.x = e[0] * inv; p0.y = e[1] * inv; p0.z = e[2] * inv; p0.w = e[3] * inv;
    p1.x = e[4] * inv; p1.y = e[5] * inv; p1.z = e[6] * inv; p1.w = e[7] * inv;
    *(float4*)&probs_out[(size_t)grp * Vx + tid * 8]     = p0;
    *(float4*)&probs_out[(size_t)grp * Vx + tid * 8 + 4] = p1;

    const int id = red_i;
    const float q = pad ? 0.f : codebook[(((g << 10) + id) << 7) + tid];
    quant_out[(size_t)row * (Gx * Dx) + g * Dx + tid] = q;

    if (tid == 0) ids_out[grp] = pad ? -1.0f : (float)id;
}

extern "C" void kernel_launch(void* const* d_in, const int* in_sizes, int n_in,
                              void* d_out, int out_size)
{
    const float* inputs = (const float*)d_in[0];   // (B,T,Din)
    const int*   pads   = (const int*)  d_in[1];   // (B,T)
    const float* gum    = (const float*)d_in[2];   // (B,T,G,V)
    const float* W      = (const float*)d_in[3];   // (Din, G*V)
    const float* bias   = (const float*)d_in[4];   // (G*V,)
    const float* cb     = (const float*)d_in[5];   // (G,V,D)

    float* out       = (float*)d_out;
    float* ids_out   = out;                                    // M*G
    float* quant_out = out + (size_t)Mx * Gx;                  // M*G*D
    float* probs_out = quant_out + (size_t)Mx * Gx * Dx;       // M*G*V

    dim3 grid(Nx / 128, Mx / 128);
    gemm_epilogue_kernel<<<grid, 256>>>(inputs, W, bias, gum);
    softmax_kernel<<<Mx * Gx, 128>>>(pads, cb, ids_out, quant_out, probs_out);
}